// round 1
// baseline (speedup 1.0000x reference)
#include <cuda_runtime.h>
#include <cuda_bf16.h>
#include <cstdint>

#define THREADS 256
#define NCOLS   8192
#define ITEMS   32          // NCOLS / THREADS
#define KTOP    64

__global__ __launch_bounds__(THREADS)
void topk_mask_kernel(const float* __restrict__ x, float* __restrict__ out) {
    const int row  = blockIdx.x;
    const int tid  = threadIdx.x;
    const int lane = tid & 31;
    const int wid  = tid >> 5;
    const unsigned lmask_lt = (1u << lane) - 1u;

    const float4* __restrict__ in4  =
        reinterpret_cast<const float4*>(x + (size_t)row * NCOLS);
    float4* __restrict__ out4 =
        reinterpret_cast<float4*>(out + (size_t)row * NCOLS);

    __shared__ unsigned hist[256];
    __shared__ unsigned wsum[8];
    __shared__ unsigned sh_prefix;
    __shared__ unsigned sh_k;
    __shared__ unsigned sh_tcnt;
    __shared__ unsigned sh_tidx[64];
    __shared__ unsigned sh_cut;

    // ---- Load row once from DRAM; keep monotone keys in registers ----
    unsigned keys[ITEMS];
    #pragma unroll
    for (int jj = 0; jj < ITEMS / 4; ++jj) {
        float4 v = in4[tid + THREADS * jj];
        unsigned u0 = __float_as_uint(v.x);
        unsigned u1 = __float_as_uint(v.y);
        unsigned u2 = __float_as_uint(v.z);
        unsigned u3 = __float_as_uint(v.w);
        keys[4 * jj + 0] = u0 ^ ((unsigned)((int)u0 >> 31) | 0x80000000u);
        keys[4 * jj + 1] = u1 ^ ((unsigned)((int)u1 >> 31) | 0x80000000u);
        keys[4 * jj + 2] = u2 ^ ((unsigned)((int)u2 >> 31) | 0x80000000u);
        keys[4 * jj + 3] = u3 ^ ((unsigned)((int)u3 >> 31) | 0x80000000u);
    }

    if (tid == 0) { sh_prefix = 0u; sh_k = KTOP; }

    // ---- 4-pass 8-bit radix select (exact 32-bit key of K-th largest) ----
    #pragma unroll
    for (int p = 0; p < 4; ++p) {
        __syncthreads();                 // (A) prev pass writes visible, hist reads done
        const unsigned prefix = sh_prefix;
        const unsigned kRem   = sh_k;
        hist[tid] = 0u;
        __syncthreads();                 // (B) hist cleared

        #pragma unroll
        for (int j = 0; j < ITEMS; ++j) {
            const unsigned key = keys[j];
            bool act;
            if (p == 0) act = true;
            else        act = (key >> (32 - 8 * p)) == prefix;

            unsigned am;
            if (p == 0) am = 0xffffffffu;
            else        am = __ballot_sync(0xffffffffu, act);

            if (am != 0u) {
                const unsigned d = act ? ((key >> (24 - 8 * p)) & 0xffu)
                                       : (256u + (unsigned)lane);   // unique, no collide
                const unsigned mm = __match_any_sync(0xffffffffu, d);
                if (act && (mm & lmask_lt) == 0u)
                    atomicAdd(&hist[d], (unsigned)__popc(mm));
            }
        }
        __syncthreads();                 // (C) histogram complete

        // Suffix-scan from top digit: thread tid handles digit (255 - tid).
        const unsigned v  = hist[255 - tid];
        unsigned sc = v;
        #pragma unroll
        for (int off = 1; off < 32; off <<= 1) {
            const unsigned y = __shfl_up_sync(0xffffffffu, sc, off);
            if (lane >= off) sc += y;
        }
        if (lane == 31) wsum[wid] = sc;
        __syncthreads();                 // (D) warp totals visible
        unsigned add = 0u;
        #pragma unroll
        for (int w = 0; w < 8; ++w) add += (w < wid) ? wsum[w] : 0u;
        const unsigned incl = sc + add;       // count of digits >= (255 - tid)
        const unsigned excl = incl - v;       // count of digits >  (255 - tid)
        if (excl < kRem && kRem <= incl) {    // exactly one thread matches
            sh_prefix = (prefix << 8) | (255u - (unsigned)tid);
            sh_k      = kRem - excl;
        }
    }
    __syncthreads();
    const unsigned T  = sh_prefix;   // exact key of the K-th largest
    const unsigned kT = sh_k;        // how many key==T elements to keep

    // ---- Tie handling: keep the kT earliest-index elements equal to T ----
    if (tid == 0) sh_tcnt = 0u;
    __syncthreads();
    #pragma unroll
    for (int j = 0; j < ITEMS; ++j) {
        if (keys[j] == T) {
            const unsigned jj  = (unsigned)(j >> 2);
            const unsigned c   = (unsigned)(j & 3);
            const unsigned col = 4u * ((unsigned)tid + THREADS * jj) + c;
            const unsigned pos = atomicAdd(&sh_tcnt, 1u);
            if (pos < 64u) sh_tidx[pos] = col;
        }
    }
    __syncthreads();
    if (tid == 0) {
        unsigned c = sh_tcnt;
        if (c > 64u) c = 64u;
        unsigned cut = 0xffffffffu;
        for (unsigned s = 0; s < kT; ++s) {       // kT-th smallest index
            unsigned mn = 0xffffffffu, mi = 0u;
            for (unsigned i = 0; i < c; ++i)
                if (sh_tidx[i] < mn) { mn = sh_tidx[i]; mi = i; }
            sh_tidx[mi] = 0xffffffffu;
            cut = mn;
        }
        sh_cut = cut;
    }
    __syncthreads();
    const unsigned cut = sh_cut;

    // ---- Masked write: decode key -> float, zero below threshold ----
    #pragma unroll
    for (int jj = 0; jj < ITEMS / 4; ++jj) {
        float4 o;
        #pragma unroll
        for (int c = 0; c < 4; ++c) {
            const unsigned key = keys[4 * jj + c];
            const unsigned col = 4u * ((unsigned)tid + THREADS * jj) + (unsigned)c;
            const bool keep = (key > T) || (key == T && col <= cut);
            const unsigned u =
                key ^ ((key & 0x80000000u) ? 0x80000000u : 0xffffffffu);
            (&o.x)[c] = keep ? __uint_as_float(u) : 0.0f;
        }
        out4[tid + THREADS * jj] = o;
    }
}

extern "C" void kernel_launch(void* const* d_in, const int* in_sizes, int n_in,
                              void* d_out, int out_size) {
    const float* x = (const float*)d_in[0];
    float* out = (float*)d_out;
    const int rows = in_sizes[0] / NCOLS;
    topk_mask_kernel<<<rows, THREADS>>>(x, out);
}

// round 2
// speedup vs baseline: 2.1272x; 2.1272x over previous
#include <cuda_runtime.h>
#include <cuda_bf16.h>
#include <cstdint>

#define THREADS 256
#define NCOLS   8192
#define FVECS   8            // float4 chunks per thread: 8*4*256 = 8192
#define KTOP    64
#define CAP     1024         // candidate buffer (Gaussian bucket ~190; 5x margin)

__device__ __forceinline__ unsigned mono(unsigned u) {
    // order-preserving fp32 -> uint key
    return u ^ ((unsigned)((int)u >> 31) | 0x80000000u);
}

__global__ __launch_bounds__(THREADS, 6)
void topk_mask_kernel(const float* __restrict__ x, float* __restrict__ out) {
    const int row  = blockIdx.x;
    const int tid  = threadIdx.x;
    const int lane = tid & 31;
    const int wid  = tid >> 5;
    const unsigned lmask_lt = (1u << lane) - 1u;

    const float4* __restrict__ in4 =
        reinterpret_cast<const float4*>(x + (size_t)row * NCOLS);
    float4* __restrict__ out4 =
        reinterpret_cast<float4*>(out + (size_t)row * NCOLS);

    __shared__ unsigned hist[256];
    __shared__ unsigned wsum[8];
    __shared__ unsigned sh_D;      // selected top-byte digit
    __shared__ unsigned sh_k;      // rank remaining within digit bucket
    __shared__ unsigned sh_cnt;    // candidate count
    __shared__ unsigned long long sh_thresh;
    __shared__ unsigned long long cand[CAP];

    hist[tid] = 0u;
    if (tid == 0) sh_cnt = 0u;
    __syncthreads();

    // ---- Phase A: 256-bin histogram of the key's top byte (row from DRAM) ----
    #pragma unroll
    for (int jj = 0; jj < FVECS; ++jj) {
        const float4 v = in4[tid + THREADS * jj];
        #pragma unroll
        for (int c = 0; c < 4; ++c) {
            const unsigned key = mono(__float_as_uint((&v.x)[c]));
            const unsigned d   = key >> 24;
            const unsigned mm  = __match_any_sync(0xffffffffu, d);
            if ((mm & lmask_lt) == 0u)
                atomicAdd(&hist[d], (unsigned)__popc(mm));
        }
    }
    __syncthreads();

    // ---- Phase B: suffix-scan from top digit; find bucket of the 64th ----
    {
        const unsigned v  = hist[255 - tid];
        unsigned sc = v;
        #pragma unroll
        for (int off = 1; off < 32; off <<= 1) {
            const unsigned y = __shfl_up_sync(0xffffffffu, sc, off);
            if (lane >= off) sc += y;
        }
        if (lane == 31) wsum[wid] = sc;
        __syncthreads();
        unsigned add = 0u;
        #pragma unroll
        for (int w = 0; w < 8; ++w) add += (w < wid) ? wsum[w] : 0u;
        const unsigned incl = sc + add;     // count with digit >= (255 - tid)
        const unsigned excl = incl - v;     // count with digit >  (255 - tid)
        if (excl < KTOP && KTOP <= incl) {  // exactly one thread hits
            sh_D = 255u - (unsigned)tid;
            sh_k = KTOP - excl;
        }
    }
    __syncthreads();
    const unsigned D    = sh_D;
    const unsigned kRem = sh_k;

    // ---- Phase C: re-read row (L2), write decided outputs, collect bucket ----
    #pragma unroll
    for (int jj = 0; jj < FVECS; ++jj) {
        const float4 v = in4[tid + THREADS * jj];
        float4 o;
        #pragma unroll
        for (int c = 0; c < 4; ++c) {
            const float    f   = (&v.x)[c];
            const unsigned key = mono(__float_as_uint(f));
            const unsigned b   = key >> 24;
            (&o.x)[c] = (b > D) ? f : 0.0f;          // candidates get 0 for now
            const bool cnd = (b == D);
            const unsigned bal = __ballot_sync(0xffffffffu, cnd);
            if (cnd) {
                const int      leader = __ffs(bal) - 1;
                const unsigned rank   = (unsigned)__popc(bal & lmask_lt);
                unsigned base = 0u;
                if (lane == leader)
                    base = atomicAdd(&sh_cnt, (unsigned)__popc(bal));
                base = __shfl_sync(bal, base, leader);
                const unsigned slot = base + rank;
                const unsigned col  = 4u * ((unsigned)tid + THREADS * jj) + (unsigned)c;
                if (slot < CAP)
                    cand[slot] = ((unsigned long long)key << 13) |
                                 (unsigned long long)(8191u - col);
            }
        }
        out4[tid + THREADS * jj] = o;
    }
    __syncthreads();

    // ---- Phase D: exact rank selection among C candidates (distinct packed) ----
    {
        unsigned C = sh_cnt;
        if (C > CAP) C = CAP;   // Gaussian: never triggers (C ~ 190)
        for (unsigned s = tid; s < C; s += THREADS) {
            const unsigned long long v = cand[s];
            unsigned r = 0u;
            for (unsigned j = 0; j < C; ++j)
                r += (cand[j] > v) ? 1u : 0u;
            if (r == kRem - 1u) sh_thresh = v;   // unique winner
        }
    }
    __syncthreads();

    // ---- Phase E: scatter kept candidates back (overwrites the zeros) ----
    {
        unsigned C = sh_cnt;
        if (C > CAP) C = CAP;
        const unsigned long long T = sh_thresh;
        float* __restrict__ orow = out + (size_t)row * NCOLS;
        for (unsigned s = tid; s < C; s += THREADS) {
            const unsigned long long v = cand[s];
            if (v >= T) {
                const unsigned col = 8191u - (unsigned)(v & 8191ull);
                const unsigned key = (unsigned)(v >> 13);
                const unsigned u   =
                    key ^ ((key & 0x80000000u) ? 0x80000000u : 0xffffffffu);
                orow[col] = __uint_as_float(u);
            }
        }
    }
}

extern "C" void kernel_launch(void* const* d_in, const int* in_sizes, int n_in,
                              void* d_out, int out_size) {
    const float* x = (const float*)d_in[0];
    float* out = (float*)d_out;
    const int rows = in_sizes[0] / NCOLS;
    topk_mask_kernel<<<rows, THREADS>>>(x, out);
}

// round 3
// speedup vs baseline: 4.1487x; 1.9503x over previous
#include <cuda_runtime.h>
#include <cuda_bf16.h>
#include <cstdint>

#define THREADS 256
#define NCOLS   8192
#define FVECS   8            // float4 chunks per thread: 8*4*256 = 8192
#define KTOP    64
#define CAP     1024
#define PIVOT   2.0f         // static pre-filter; generic fallback if it misfires

__device__ __forceinline__ unsigned mono(unsigned u) {
    return u ^ ((unsigned)((int)u >> 31) | 0x80000000u);
}

__global__ __launch_bounds__(THREADS, 6)
void topk_mask_kernel(const float* __restrict__ x, float* __restrict__ out) {
    const int row  = blockIdx.x;
    const int tid  = threadIdx.x;
    const int lane = tid & 31;
    const int wid  = tid >> 5;

    const float4* __restrict__ in4 =
        reinterpret_cast<const float4*>(x + (size_t)row * NCOLS);
    float4* __restrict__ out4 =
        reinterpret_cast<float4*>(out + (size_t)row * NCOLS);
    float* __restrict__ orow = out + (size_t)row * NCOLS;

    __shared__ unsigned hist[256];
    __shared__ unsigned wsum[8];
    __shared__ unsigned sh_cnt;
    __shared__ unsigned long long sh_T;
    __shared__ unsigned long long cand[CAP];

    // ---- Phase 0: blast zeros to the output row (no dependencies) ----
    const float4 z = make_float4(0.f, 0.f, 0.f, 0.f);
    #pragma unroll
    for (int jj = 0; jj < FVECS; ++jj)
        out4[tid + THREADS * jj] = z;

    if (tid == 0) sh_cnt = 0u;
    __syncthreads();

    // ---- Phase 1: single read pass, cheap pre-filter, push candidates ----
    #pragma unroll
    for (int jj = 0; jj < FVECS; ++jj) {
        const float4 v = in4[tid + THREADS * jj];
        #pragma unroll
        for (int c = 0; c < 4; ++c) {
            const float f = (&v.x)[c];
            if (f > PIVOT) {
                const unsigned col = 4u * ((unsigned)tid + THREADS * jj) + (unsigned)c;
                const unsigned pos = atomicAdd(&sh_cnt, 1u);
                if (pos < CAP)   // positive floats: raw bits are order-preserving
                    cand[pos] = ((unsigned long long)__float_as_uint(f) << 13) |
                                (unsigned long long)(8191u - col);
            }
        }
    }
    __syncthreads();
    const unsigned cnt = sh_cnt;

    if (cnt >= KTOP && cnt <= CAP) {
        // ---- Phase 2: exact rank-64 among candidates (unique packed keys) ----
        for (unsigned s = tid; s < cnt; s += THREADS) {
            const unsigned long long v = cand[s];
            unsigned r = 0u;
            for (unsigned j = 0; j < cnt; ++j)
                r += (cand[j] > v) ? 1u : 0u;
            if (r == KTOP - 1u) sh_T = v;
        }
        __syncthreads();
        const unsigned long long T = sh_T;

        // ---- Phase 3: scatter the 64 kept values over the zeros ----
        for (unsigned s = tid; s < cnt; s += THREADS) {
            const unsigned long long v = cand[s];
            if (v >= T) {
                const unsigned col = 8191u - (unsigned)(v & 8191ull);
                orow[col] = __uint_as_float((unsigned)(v >> 13));
            }
        }
        return;
    }

    // ================= Generic fallback (never taken for N(0,1) data) ======
    // 4-pass 8-bit radix select with L2 re-reads; exact tie-break by column.
    __shared__ unsigned sh_prefix, sh_kk, sh_tcnt, sh_cut;
    if (tid == 0) { sh_prefix = 0u; sh_kk = KTOP; }

    for (int p = 0; p < 4; ++p) {
        __syncthreads();
        const unsigned prefix = sh_prefix;
        const unsigned kRem   = sh_kk;
        hist[tid] = 0u;
        __syncthreads();
        for (int jj = 0; jj < FVECS; ++jj) {
            const float4 v = in4[tid + THREADS * jj];
            #pragma unroll
            for (int c = 0; c < 4; ++c) {
                const unsigned key = mono(__float_as_uint((&v.x)[c]));
                const bool act = (p == 0) || ((key >> (32 - 8 * p)) == prefix);
                if (act)
                    atomicAdd(&hist[(key >> (24 - 8 * p)) & 0xffu], 1u);
            }
        }
        __syncthreads();
        const unsigned v  = hist[255 - tid];
        unsigned sc = v;
        #pragma unroll
        for (int off = 1; off < 32; off <<= 1) {
            const unsigned y = __shfl_up_sync(0xffffffffu, sc, off);
            if (lane >= off) sc += y;
        }
        if (lane == 31) wsum[wid] = sc;
        __syncthreads();
        unsigned add = 0u;
        #pragma unroll
        for (int w = 0; w < 8; ++w) add += (w < wid) ? wsum[w] : 0u;
        const unsigned incl = sc + add;
        const unsigned excl = incl - v;
        if (excl < kRem && kRem <= incl) {
            sh_prefix = (prefix << 8) | (255u - (unsigned)tid);
            sh_kk     = kRem - excl;
        }
    }
    __syncthreads();
    const unsigned Tk = sh_prefix;
    const unsigned kT = sh_kk;

    // collect columns of key == Tk, pick kT-th smallest as cut
    unsigned* tcol = (unsigned*)cand;
    if (tid == 0) sh_tcnt = 0u;
    __syncthreads();
    for (int jj = 0; jj < FVECS; ++jj) {
        const float4 v = in4[tid + THREADS * jj];
        #pragma unroll
        for (int c = 0; c < 4; ++c) {
            const unsigned key = mono(__float_as_uint((&v.x)[c]));
            if (key == Tk) {
                const unsigned col = 4u * ((unsigned)tid + THREADS * jj) + (unsigned)c;
                const unsigned pos = atomicAdd(&sh_tcnt, 1u);
                if (pos < 2u * CAP) tcol[pos] = col;
            }
        }
    }
    __syncthreads();
    if (tid == 0) {
        unsigned c = sh_tcnt; if (c > 2u * CAP) c = 2u * CAP;
        unsigned cut = 0xffffffffu;
        for (unsigned s = 0; s < kT; ++s) {
            unsigned mn = 0xffffffffu, mi = 0u;
            for (unsigned i = 0; i < c; ++i)
                if (tcol[i] < mn) { mn = tcol[i]; mi = i; }
            tcol[mi] = 0xffffffffu;
            cut = mn;
        }
        sh_cut = cut;
    }
    __syncthreads();
    const unsigned cut = sh_cut;

    for (int jj = 0; jj < FVECS; ++jj) {
        const float4 v = in4[tid + THREADS * jj];
        float4 o;
        #pragma unroll
        for (int c = 0; c < 4; ++c) {
            const unsigned key = mono(__float_as_uint((&v.x)[c]));
            const unsigned col = 4u * ((unsigned)tid + THREADS * jj) + (unsigned)c;
            const bool keep = (key > Tk) || (key == Tk && col <= cut);
            (&o.x)[c] = keep ? (&v.x)[c] : 0.0f;
        }
        out4[tid + THREADS * jj] = o;
    }
}

extern "C" void kernel_launch(void* const* d_in, const int* in_sizes, int n_in,
                              void* d_out, int out_size) {
    const float* x = (const float*)d_in[0];
    float* out = (float*)d_out;
    const int rows = in_sizes[0] / NCOLS;
    topk_mask_kernel<<<rows, THREADS>>>(x, out);
}

// round 4
// speedup vs baseline: 5.2390x; 1.2628x over previous
#include <cuda_runtime.h>
#include <cuda_bf16.h>
#include <cstdint>

#define THREADS 256
#define NCOLS   8192
#define FVECS   8            // float4 chunks per thread: 8*4*256 = 8192
#define KTOP    64
#define CAP     1024         // candidate buffer (expected ~186)
#define MCAP    768          // marked-vec4 buffer (expected ~170)
#define TBCAP   128          // in-bin buffer for final exact rank
#define PIVOT   2.0f

__device__ __forceinline__ unsigned mono(unsigned u) {
    return u ^ ((unsigned)((int)u >> 31) | 0x80000000u);
}

__global__ __launch_bounds__(THREADS, 6)
void topk_mask_kernel(const float* __restrict__ x, float* __restrict__ out) {
    const int row  = blockIdx.x;
    const int tid  = threadIdx.x;
    const int lane = tid & 31;
    const int wid  = tid >> 5;

    const float4* __restrict__ in4 =
        reinterpret_cast<const float4*>(x + (size_t)row * NCOLS);
    float4* __restrict__ out4 =
        reinterpret_cast<float4*>(out + (size_t)row * NCOLS);
    float* __restrict__ orow = out + (size_t)row * NCOLS;

    __shared__ unsigned hist[256];
    __shared__ unsigned wsum[8];
    __shared__ unsigned sh_cnt, sh_mcnt, sh_B, sh_kB, sh_tc;
    __shared__ unsigned long long sh_T;
    __shared__ unsigned long long cand[CAP];
    __shared__ unsigned long long mbuf[MCAP / 2];   // marks (u32) / tb (u64) reuse
    unsigned* marks = reinterpret_cast<unsigned*>(mbuf);

    if (tid == 0) { sh_cnt = 0u; sh_mcnt = 0u; sh_tc = 0u; }
    __syncthreads();

    // ---- Phase 1: single fused pass: zero output, mark vec4s with any f>2 ----
    const float4 z = make_float4(0.f, 0.f, 0.f, 0.f);
    #pragma unroll
    for (int jj = 0; jj < FVECS; ++jj) {
        const int idx = tid + THREADS * jj;
        const float4 v = in4[idx];
        out4[idx] = z;
        const float m = fmaxf(fmaxf(v.x, v.y), fmaxf(v.z, v.w));
        if (m > PIVOT) {
            const unsigned pos = atomicAdd(&sh_mcnt, 1u);
            if (pos < MCAP) marks[pos] = (unsigned)idx;
        }
    }
    __syncthreads();
    const unsigned mcnt = sh_mcnt;

    // ---- Phase 2: rescan marked vec4s (L1/L2 hits), extract exact candidates ----
    if (mcnt <= MCAP) {
        for (unsigned s = tid; s < mcnt; s += THREADS) {
            const unsigned idx = marks[s];
            const float4 v = in4[idx];
            #pragma unroll
            for (int c = 0; c < 4; ++c) {
                const float f = (&v.x)[c];
                if (f > PIVOT) {
                    const unsigned pos = atomicAdd(&sh_cnt, 1u);
                    if (pos < CAP)
                        cand[pos] =
                            ((unsigned long long)__float_as_uint(f) << 13) |
                            (unsigned long long)(8191u - (4u * idx + (unsigned)c));
                }
            }
        }
    }
    __syncthreads();
    const unsigned cnt = sh_cnt;

    if (mcnt <= MCAP && cnt >= KTOP && cnt <= CAP) {
        // ---- Phase 3: 128-bin monotone histogram over candidate bits ----
        hist[tid] = 0u;
        __syncthreads();
        for (unsigned s = tid; s < cnt; s += THREADS) {
            const unsigned bits = (unsigned)(cand[s] >> 13);
            unsigned d = (bits - 0x40000000u) >> 17;
            if (d > 127u) d = 127u;
            atomicAdd(&hist[d], 1u);
        }
        __syncthreads();

        // suffix-scan from top bin (threads 0..127 handle bin 127-tid)
        unsigned v = 0u, sc = 0u;
        if (tid < 128) {
            v = hist[127 - tid];
            sc = v;
            #pragma unroll
            for (int off = 1; off < 32; off <<= 1) {
                const unsigned y = __shfl_up_sync(0xffffffffu, sc, off);
                if (lane >= off) sc += y;
            }
            if (lane == 31) wsum[wid] = sc;
        }
        __syncthreads();
        if (tid < 128) {
            unsigned add = 0u;
            #pragma unroll
            for (int w = 0; w < 4; ++w) add += (w < wid) ? wsum[w] : 0u;
            const unsigned incl = sc + add;
            const unsigned excl = incl - v;
            if (excl < KTOP && KTOP <= incl) {
                sh_B  = 127u - (unsigned)tid;
                sh_kB = KTOP - excl;
            }
        }
        __syncthreads();
        const unsigned B  = sh_B;
        const unsigned kB = sh_kB;

        // ---- Phase 4: collect in-bin candidates (expected 2-5) ----
        unsigned long long* tb = mbuf;   // marks no longer needed
        for (unsigned s = tid; s < cnt; s += THREADS) {
            const unsigned long long cv = cand[s];
            const unsigned bits = (unsigned)(cv >> 13);
            unsigned d = (bits - 0x40000000u) >> 17;
            if (d > 127u) d = 127u;
            if (d == B) {
                const unsigned p = atomicAdd(&sh_tc, 1u);
                if (p < TBCAP) tb[p] = cv;
            }
        }
        __syncthreads();
        const unsigned tc = sh_tc;

        if (tc <= TBCAP) {
            // exact rank among the few in-bin candidates (unique packed keys)
            for (unsigned s = tid; s < tc; s += THREADS) {
                const unsigned long long vv = tb[s];
                unsigned r = 0u;
                for (unsigned j = 0; j < tc; ++j)
                    r += (tb[j] > vv) ? 1u : 0u;
                if (r == kB - 1u) sh_T = vv;
            }
            __syncthreads();
            const unsigned long long T = sh_T;

            // ---- Phase 5: scatter the 64 kept values over the zeros ----
            for (unsigned s = tid; s < cnt; s += THREADS) {
                const unsigned long long cv = cand[s];
                const unsigned bits = (unsigned)(cv >> 13);
                unsigned d = (bits - 0x40000000u) >> 17;
                if (d > 127u) d = 127u;
                if (d > B || (d == B && cv >= T)) {
                    const unsigned col = 8191u - (unsigned)(cv & 8191ull);
                    orow[col] = __uint_as_float(bits);
                }
            }
            return;
        }
        // tc overflow -> fall through to generic fallback
    }

    // ================= Generic fallback (never taken for N(0,1) data) ======
    __shared__ unsigned sh_prefix, sh_kk, sh_tcnt, sh_cut;
    if (tid == 0) { sh_prefix = 0u; sh_kk = KTOP; }

    for (int p = 0; p < 4; ++p) {
        __syncthreads();
        const unsigned prefix = sh_prefix;
        const unsigned kRem   = sh_kk;
        hist[tid] = 0u;
        __syncthreads();
        for (int jj = 0; jj < FVECS; ++jj) {
            const float4 v = in4[tid + THREADS * jj];
            #pragma unroll
            for (int c = 0; c < 4; ++c) {
                const unsigned key = mono(__float_as_uint((&v.x)[c]));
                const bool act = (p == 0) || ((key >> (32 - 8 * p)) == prefix);
                if (act)
                    atomicAdd(&hist[(key >> (24 - 8 * p)) & 0xffu], 1u);
            }
        }
        __syncthreads();
        const unsigned v  = hist[255 - tid];
        unsigned sc = v;
        #pragma unroll
        for (int off = 1; off < 32; off <<= 1) {
            const unsigned y = __shfl_up_sync(0xffffffffu, sc, off);
            if (lane >= off) sc += y;
        }
        if (lane == 31) wsum[wid] = sc;
        __syncthreads();
        unsigned add = 0u;
        #pragma unroll
        for (int w = 0; w < 8; ++w) add += (w < wid) ? wsum[w] : 0u;
        const unsigned incl = sc + add;
        const unsigned excl = incl - v;
        if (excl < kRem && kRem <= incl) {
            sh_prefix = (prefix << 8) | (255u - (unsigned)tid);
            sh_kk     = kRem - excl;
        }
    }
    __syncthreads();
    const unsigned Tk = sh_prefix;
    const unsigned kT = sh_kk;

    unsigned* tcol = (unsigned*)cand;
    if (tid == 0) sh_tcnt = 0u;
    __syncthreads();
    for (int jj = 0; jj < FVECS; ++jj) {
        const float4 v = in4[tid + THREADS * jj];
        #pragma unroll
        for (int c = 0; c < 4; ++c) {
            const unsigned key = mono(__float_as_uint((&v.x)[c]));
            if (key == Tk) {
                const unsigned col = 4u * ((unsigned)tid + THREADS * jj) + (unsigned)c;
                const unsigned pos = atomicAdd(&sh_tcnt, 1u);
                if (pos < 2u * CAP) tcol[pos] = col;
            }
        }
    }
    __syncthreads();
    if (tid == 0) {
        unsigned c = sh_tcnt; if (c > 2u * CAP) c = 2u * CAP;
        unsigned cut = 0xffffffffu;
        for (unsigned s = 0; s < kT; ++s) {
            unsigned mn = 0xffffffffu, mi = 0u;
            for (unsigned i = 0; i < c; ++i)
                if (tcol[i] < mn) { mn = tcol[i]; mi = i; }
            tcol[mi] = 0xffffffffu;
            cut = mn;
        }
        sh_cut = cut;
    }
    __syncthreads();
    const unsigned cut = sh_cut;

    for (int jj = 0; jj < FVECS; ++jj) {
        const float4 v = in4[tid + THREADS * jj];
        float4 o;
        #pragma unroll
        for (int c = 0; c < 4; ++c) {
            const unsigned key = mono(__float_as_uint((&v.x)[c]));
            const unsigned col = 4u * ((unsigned)tid + THREADS * jj) + (unsigned)c;
            const bool keep = (key > Tk) || (key == Tk && col <= cut);
            (&o.x)[c] = keep ? (&v.x)[c] : 0.0f;
        }
        out4[tid + THREADS * jj] = o;
    }
}

extern "C" void kernel_launch(void* const* d_in, const int* in_sizes, int n_in,
                              void* d_out, int out_size) {
    const float* x = (const float*)d_in[0];
    float* out = (float*)d_out;
    const int rows = in_sizes[0] / NCOLS;
    topk_mask_kernel<<<rows, THREADS>>>(x, out);
}